// round 7
// baseline (speedup 1.0000x reference)
#include <cuda_runtime.h>
#include <cuda_bf16.h>
#include <stdint.h>

#define THREADS 512
#define TRm     128
#define HDIM    128
#define EDIM    64
#define PDIM    95
#define NLAYER  6
#define NBLK    2
#define RSTR    136
#define LFE     (832*RSTR*2)
#define OFF_CTX 0
#define OFF_BLK0 (64*RSTR*2)
#define BLK_SZ  (320*RSTR*2)
#define OFF_W2  (128*RSTR*2)
#define OFF_WC  (256*RSTR*2)
#define OFF_OUT (704*RSTR*2)

__device__ __align__(16) __nv_bfloat16 g_wb[NLAYER*LFE];   // 2.7MB weight scratch

#define CHUNK_B 17408                // 32 krows x 272B (hi) + same (lo)
#define RING_B  (3*CHUNK_B)          // 52224
#define AH_B    RING_B               // A hi: 128 x 272B = 34816
#define AL_B    (AH_B+34816)
#define EH_B    (AL_B+34816)         // E hi: 128 x 144B = 18432
#define EL_B    (EH_B+18432)
#define Z_B     (EL_B+18432)
#define LAD_B   (Z_B+512)
#define SMEM_B  (LAD_B+512)          // 159744 B -> 1 CTA/SM
#define ASTR_A  272
#define ASTR_E  144
#define LDP     97

// ---------------- PTX helpers ----------------
__device__ __forceinline__ void cp16(void* dst, const void* src){
  unsigned d = (unsigned)__cvta_generic_to_shared(dst);
  asm volatile("cp.async.cg.shared.global [%0], [%1], 16;\n" :: "r"(d), "l"(src));
}
__device__ __forceinline__ void cp_commit(){ asm volatile("cp.async.commit_group;\n" ::: "memory"); }
template<int N> __device__ __forceinline__ void cp_wait(){
  asm volatile("cp.async.wait_group %0;\n" :: "n"(N) : "memory");
}
__device__ __forceinline__ void ldsm4(uint32_t a, uint32_t& r0, uint32_t& r1, uint32_t& r2, uint32_t& r3){
  asm volatile("ldmatrix.sync.aligned.m8n8.x4.shared.b16 {%0,%1,%2,%3}, [%4];"
    : "=r"(r0),"=r"(r1),"=r"(r2),"=r"(r3) : "r"(a));
}
__device__ __forceinline__ void ldsm4t(uint32_t a, uint32_t& r0, uint32_t& r1, uint32_t& r2, uint32_t& r3){
  asm volatile("ldmatrix.sync.aligned.m8n8.x4.trans.shared.b16 {%0,%1,%2,%3}, [%4];"
    : "=r"(r0),"=r"(r1),"=r"(r2),"=r"(r3) : "r"(a));
}
__device__ __forceinline__ void mma16816(float* c, uint32_t a0,uint32_t a1,uint32_t a2,uint32_t a3,
                                         uint32_t b0, uint32_t b1){
  asm volatile("mma.sync.aligned.m16n8k16.row.col.f32.bf16.bf16.f32 "
    "{%0,%1,%2,%3},{%4,%5,%6,%7},{%8,%9},{%0,%1,%2,%3};"
    : "+f"(c[0]),"+f"(c[1]),"+f"(c[2]),"+f"(c[3])
    : "r"(a0),"r"(a1),"r"(a2),"r"(a3),"r"(b0),"r"(b1));
}
__device__ __forceinline__ uint32_t bfpack(float lo, float hi){   // low half <- lo
  uint32_t r; asm("cvt.rn.bf16x2.f32 %0, %1, %2;" : "=r"(r) : "f"(hi), "f"(lo)); return r;
}
__device__ __forceinline__ float eluf(float x){ return x > 0.f ? x : (__expf(x) - 1.f); }
__device__ __forceinline__ float sigmoidf_(float x){ return 1.f / (1.f + __expf(-x)); }
__device__ __forceinline__ float softplusf_(float x){ return fmaxf(x, 0.f) + __logf(1.f + __expf(-fabsf(x))); }
__device__ __forceinline__ void stage4(float* dst, const float* __restrict__ src, int n){
  const float4* s = (const float4*)src; float4* d = (float4*)dst;
  for (int i = threadIdx.x; i < (n >> 2); i += THREADS) d[i] = s[i];
}

// ---------------- tensor GEMM: acc[128][128] += Asplit @ Wsplit, W via cp.async ring ----------------
template<int KD, int ASTRB>
__device__ __forceinline__ void gemm_t(char* smc, uint32_t s32,
    uint32_t ahBase, uint32_t alBase, const __nv_bfloat16* __restrict__ Wg,
    float acc[8][4], int wm, int wn, int lane, int tid)
{
  constexpr int NC = KD/32;
  const char* Wh = (const char*)Wg;
  const char* Wl = (const char*)(Wg + KD*RSTR);
  #define STAGE_T(c, b) do{                                   \
    char* _db = smc + (b)*CHUNK_B;                            \
    const char* _sh = Wh + (c)*8704;                          \
    const char* _sl = Wl + (c)*8704;                          \
    for (int _i = tid; _i < 544; _i += THREADS){              \
      cp16(_db + _i*16, _sh + _i*16);                         \
      cp16(_db + 8704 + _i*16, _sl + _i*16);                  \
    } }while(0)

  STAGE_T(0,0); cp_commit();
  if (NC > 1) STAGE_T(1,1);
  cp_commit();

  int off16 = lane & 15, g16 = (lane >> 4) * 16;
  uint32_t aH = ahBase + (16*wm + off16)*ASTRB + g16;
  uint32_t aL = alBase + (16*wm + off16)*ASTRB + g16;
  uint32_t bB = s32 + off16*272 + wn*128 + g16;

  #pragma unroll 1
  for (int c = 0; c < NC; c++){
    cp_wait<1>();
    __syncthreads();                       // publish chunk c; compute c-1 done
    if (c + 2 < NC) STAGE_T(c+2, (c+2)%3);
    cp_commit();
    uint32_t bChunk = bB + (c%3)*CHUNK_B;
    #pragma unroll
    for (int ks = 0; ks < 2; ks++){
      int kb = (c*2 + ks)*32;
      uint32_t A0,A1,A2,A3, L0,L1,L2,L3;
      ldsm4(aH + kb, A0,A1,A2,A3);
      ldsm4(aL + kb, L0,L1,L2,L3);
      uint32_t bRow = bChunk + ks*4352;
      #pragma unroll
      for (int np = 0; np < 4; np++){
        uint32_t H0,H1,H2,H3, P0,P1,P2,P3;
        ldsm4t(bRow + np*32,        H0,H1,H2,H3);
        ldsm4t(bRow + 8704 + np*32, P0,P1,P2,P3);
        mma16816(acc[2*np],   A0,A1,A2,A3, H0,H1);
        mma16816(acc[2*np+1], A0,A1,A2,A3, H2,H3);
        mma16816(acc[2*np],   A0,A1,A2,A3, P0,P1);
        mma16816(acc[2*np+1], A0,A1,A2,A3, P2,P3);
        mma16816(acc[2*np],   L0,L1,L2,L3, H0,H1);
        mma16816(acc[2*np+1], L0,L1,L2,L3, H2,H3);
      }
    }
  }
  __syncthreads();                         // close pipe-to-pipe seam
  #undef STAGE_T
}

// epilogue: per-warp 16x64 fp32 tile -> bf16 hi/lo A tiles
__device__ __forceinline__ void write_tiles(const float v[8][4], bool do_elu,
    char* smc, int wm, int wn, int lane)
{
  char* Ahp = smc + AH_B; char* Alp = smc + AL_B;
  int r0 = 16*wm + (lane>>2), r1 = r0 + 8;
  #pragma unroll
  for (int t = 0; t < 8; t++){
    int cc = 64*wn + t*8 + 2*(lane&3);
    float x0 = v[t][0], x1 = v[t][1], y0 = v[t][2], y1 = v[t][3];
    if (do_elu){ x0=eluf(x0); x1=eluf(x1); y0=eluf(y0); y1=eluf(y1); }
    float x0h=__bfloat162float(__float2bfloat16(x0));
    float x1h=__bfloat162float(__float2bfloat16(x1));
    float y0h=__bfloat162float(__float2bfloat16(y0));
    float y1h=__bfloat162float(__float2bfloat16(y1));
    *(uint32_t*)(Ahp + r0*ASTR_A + cc*2) = bfpack(x0, x1);
    *(uint32_t*)(Alp + r0*ASTR_A + cc*2) = bfpack(x0-x0h, x1-x1h);
    *(uint32_t*)(Ahp + r1*ASTR_A + cc*2) = bfpack(y0, y1);
    *(uint32_t*)(Alp + r1*ASTR_A + cc*2) = bfpack(y0-y0h, y1-y1h);
  }
}

__device__ __forceinline__ void init_bias(float a[8][4], const float* __restrict__ b,
                                          int wn, int lane, int maxc){
  #pragma unroll
  for (int t = 0; t < 8; t++){
    int cc = 64*wn + t*8 + 2*(lane&3);
    float v0 = (cc < maxc) ? b[cc] : 0.f;
    float v1 = (cc+1 < maxc) ? b[cc+1] : 0.f;
    a[t][0]=a[t][2]=v0; a[t][1]=a[t][3]=v1;
  }
}

// ---------------- rational-quadratic spline ----------------
__device__ float spline_fwd(const float* __restrict__ p, float z, float* lad_out){
  const float TBv = 6.0f, MINB = 1e-3f;
  const float C1  = 1.0f - 32.0f * MINB;
  const float ISC = 0.088388347648318447f;  // 1/sqrt(128)
  bool inside = (z >= -TBv) && (z <= TBv);
  float yc = fminf(fmaxf(z, -TBv), TBv);

  float mw = -1e30f;
  #pragma unroll 8
  for (int i = 0; i < 32; i++) mw = fmaxf(mw, p[i] * ISC);
  float ssw = 0.f;
  #pragma unroll 8
  for (int i = 0; i < 32; i++) ssw += __expf(p[i] * ISC - mw);
  float isw = C1 / ssw;

  int idx = -1;
  float cw_k = 0.f, cw_k1 = 0.f, cum = 0.f, prevb = -TBv;
  for (int i = 0; i < 31; i++){
    cum += MINB + __expf(p[i] * ISC - mw) * isw;
    float b = 12.f * cum - 6.f;
    if (yc < b){ idx = i; cw_k = prevb; cw_k1 = b; break; }
    prevb = b;
  }
  if (idx < 0){ idx = 31; cw_k = prevb; cw_k1 = TBv; }

  float mh = -1e30f;
  #pragma unroll 8
  for (int i = 0; i < 32; i++) mh = fmaxf(mh, p[32+i] * ISC);
  float ssh = 0.f;
  #pragma unroll 8
  for (int i = 0; i < 32; i++) ssh += __expf(p[32+i] * ISC - mh);
  float ish = C1 / ssh;
  float cum2 = 0.f;
  for (int i = 0; i < idx; i++) cum2 += MINB + __expf(p[32+i] * ISC - mh) * ish;
  float ch_k = 12.f * cum2 - 6.f;
  cum2 += MINB + __expf(p[32+idx] * ISC - mh) * ish;
  float ch_k1 = (idx == 31) ? TBv : (12.f * cum2 - 6.f);

  float dk  = (idx == 0)  ? 1.0f : (MINB + softplusf_(p[64 + idx - 1]));
  float dk1 = (idx == 31) ? 1.0f : (MINB + softplusf_(p[64 + idx]));

  float w_k = cw_k1 - cw_k, h_k = ch_k1 - ch_k;
  float s_k = h_k / w_k;
  float th = (yc - cw_k) / w_k;
  float th1m = th * (1.f - th);
  float num = h_k * (s_k * th * th + dk * th1m);
  float den = s_k + (dk + dk1 - 2.f * s_k) * th1m;
  float outv = ch_k + num / den;
  float omt = 1.f - th;
  float dnum = s_k * s_k * (dk1 * th * th + 2.f * s_k * th1m + dk * omt * omt);
  float lad = __logf(dnum) - 2.f * __logf(den);
  *lad_out = inside ? lad : 0.f;
  return inside ? outv : z;
}

// ---------------- prep: fp32 weights -> padded bf16 hi/lo ----------------
extern "C" __global__ void prep_kernel(const float* __restrict__ ctx_W,
  const float* __restrict__ bW1, const float* __restrict__ bW2,
  const float* __restrict__ bWc, const float* __restrict__ out_W)
{
  int b = blockIdx.x;              // 0 .. 6*832-1
  int l = b / 832, r = b % 832;
  const float* src; long off; int K, row, nsrc = 128;
  if (r < 64){
    src = ctx_W + (long)l*64*128 + (long)r*128; off = (long)l*LFE + OFF_CTX; K=64; row=r;
  } else if (r < 704){
    int rb = r - 64, j = rb / 320, rr = rb % 320;
    long base = (long)l*LFE + OFF_BLK0 + (long)j*BLK_SZ;
    if (rr < 128){      src = bW1 + (long)(l*NBLK+j)*16384 + (long)rr*128;       off = base;          K=128; row=rr; }
    else if (rr < 256){ src = bW2 + (long)(l*NBLK+j)*16384 + (long)(rr-128)*128; off = base + OFF_W2; K=128; row=rr-128; }
    else {              src = bWc + (long)(l*NBLK+j)*8192  + (long)(rr-256)*128; off = base + OFF_WC; K=64;  row=rr-256; }
  } else {
    int rr = r - 704;
    src = out_W + (long)l*128*95 + (long)rr*95; off = (long)l*LFE + OFF_OUT; K=128; row=rr; nsrc=95;
  }
  __nv_bfloat16* hi = g_wb + off + (long)row*RSTR;
  __nv_bfloat16* lo = hi + (long)K*RSTR;
  for (int c = threadIdx.x; c < RSTR; c += blockDim.x){
    float w = (c < nsrc) ? src[c] : 0.f;
    __nv_bfloat16 hh = __float2bfloat16(w);
    hi[c] = hh;
    lo[c] = __float2bfloat16(w - __bfloat162float(hh));
  }
}

// ---------------- fused network kernel ----------------
extern "C" __global__ void __launch_bounds__(THREADS, 1)
nsf_kernel(const float* __restrict__ y,     const float* __restrict__ ctx,
           const float* __restrict__ eW1,   const float* __restrict__ eb1,
           const float* __restrict__ eW2,   const float* __restrict__ eb2,
           const float* __restrict__ eW3,   const float* __restrict__ eb3,
           const float* __restrict__ init_b,const float* __restrict__ ctx_b,
           const float* __restrict__ bb1,   const float* __restrict__ bb2,
           const float* __restrict__ bbc,   const float* __restrict__ out_b,
           float* __restrict__ out)
{
  extern __shared__ char smc[];
  uint32_t s32 = (uint32_t)__cvta_generic_to_shared(smc);
  int tid = threadIdx.x, lane = tid & 31, wid = tid >> 5;
  int wm = wid & 7, wn = wid >> 3;       // 8 x 2 warp grid: 16-row x 64-col tiles
  int row0 = blockIdx.x * TRm;

  float* sZ   = (float*)(smc + Z_B);
  float* sLad = (float*)(smc + LAD_B);
  if (tid < TRm){ sZ[tid] = y[row0 + tid]; sLad[tid] = 0.f; }

  // ---------- embedding: ctx[2] -> 64 -> 64 -> 64 (fp32) ----------
  float* sWf  = (float*)smc;
  float* bufA = (float*)(smc + AH_B);    // [128][65] fp32 = 33280B
  float* bufB = (float*)(smc + AL_B);
  __nv_bfloat16* sEh = (__nv_bfloat16*)(smc + EH_B);
  __nv_bfloat16* sEl = (__nv_bfloat16*)(smc + EL_B);

  for (int i = tid; i < TRm*64; i += THREADS){
    int r = i >> 6, c = i & 63;
    float c0 = ctx[(row0 + r)*2], c1 = ctx[(row0 + r)*2 + 1];
    bufA[r*65 + c] = eluf(c0*eW1[c] + c1*eW1[64 + c] + eb1[c]);
  }
  stage4(sWf, eW2, 4096);
  __syncthreads();
  for (int i = tid; i < TRm*64; i += THREADS){
    int r = i >> 6, c = i & 63;
    float acc = eb2[c];
    #pragma unroll 8
    for (int k = 0; k < 64; k++) acc += bufA[r*65 + k] * sWf[k*64 + c];
    bufB[r*65 + c] = eluf(acc);
  }
  __syncthreads();
  stage4(sWf, eW3, 4096);
  __syncthreads();
  for (int i = tid; i < TRm*64; i += THREADS){
    int r = i >> 6, c = i & 63;
    float acc = eb3[c];
    #pragma unroll 8
    for (int k = 0; k < 64; k++) acc += bufB[r*65 + k] * sWf[k*64 + c];
    float v = eluf(acc);
    __nv_bfloat16 hh = __float2bfloat16(v);
    sEh[r*72 + c] = hh;
    sEl[r*72 + c] = __float2bfloat16(v - __bfloat162float(hh));
  }
  __syncthreads();

  uint32_t ahA = s32 + AH_B, alA = s32 + AL_B;
  uint32_t ahE = s32 + EH_B, alE = s32 + EL_B;

  // ---------- layers ----------
  #pragma unroll 1
  for (int l = 0; l < NLAYER; l++){
    const __nv_bfloat16* LW = g_wb + (size_t)l*LFE;
    float h[8][4];
    {
      const float* b1 = init_b + l*HDIM;
      const float* b2 = ctx_b  + l*HDIM;
      #pragma unroll
      for (int t = 0; t < 8; t++){
        int cc = 64*wn + t*8 + 2*(lane&3);
        h[t][0] = h[t][2] = b1[cc]   + b2[cc];
        h[t][1] = h[t][3] = b1[cc+1] + b2[cc+1];
      }
      gemm_t<EDIM, ASTR_E>(smc, s32, ahE, alE, LW + OFF_CTX, h, wm, wn, lane, tid);
    }

    #pragma unroll 1
    for (int j = 0; j < NBLK; j++){
      const __nv_bfloat16* WB = LW + OFF_BLK0 + (size_t)j*BLK_SZ;
      write_tiles(h, true, smc, wm, wn, lane);               // tiles = elu(h)

      float a1[8][4];
      init_bias(a1, bb1 + (l*NBLK + j)*HDIM, wn, lane, HDIM);
      gemm_t<HDIM, ASTR_A>(smc, s32, ahA, alA, WB, a1, wm, wn, lane, tid);

      write_tiles(a1, true, smc, wm, wn, lane);              // tiles = elu(t1)

      float a2[8][4];
      init_bias(a2, bb2 + (l*NBLK + j)*HDIM, wn, lane, HDIM);
      gemm_t<HDIM, ASTR_A>(smc, s32, ahA, alA, WB + OFF_W2, a2, wm, wn, lane, tid);

      float a3[8][4];
      init_bias(a3, bbc + (l*NBLK + j)*HDIM, wn, lane, HDIM);
      gemm_t<EDIM, ASTR_E>(smc, s32, ahE, alE, WB + OFF_WC, a3, wm, wn, lane, tid);

      #pragma unroll
      for (int t = 0; t < 8; t++)
        #pragma unroll
        for (int u = 0; u < 4; u++)
          h[t][u] += a2[t][u] * sigmoidf_(a3[t][u]);
    }

    // ---------- out gemm: p = h @ out_W + out_b (N padded to 128) ----------
    {
      write_tiles(h, false, smc, wm, wn, lane);
      float po[8][4];
      init_bias(po, out_b + l*PDIM, wn, lane, PDIM);
      gemm_t<HDIM, ASTR_A>(smc, s32, ahA, alA, LW + OFF_OUT, po, wm, wn, lane, tid);

      float* pbuf = (float*)(smc + AH_B);      // [128][LDP] fp32 = 49664B (A hi+lo region)
      int r0 = 16*wm + (lane>>2), r1 = r0 + 8;
      #pragma unroll
      for (int t = 0; t < 8; t++){
        int cc = 64*wn + t*8 + 2*(lane&3);
        if (cc < PDIM){ pbuf[r0*LDP + cc] = po[t][0]; pbuf[r1*LDP + cc] = po[t][2]; }
        if (cc+1 < PDIM){ pbuf[r0*LDP + cc+1] = po[t][1]; pbuf[r1*LDP + cc+1] = po[t][3]; }
      }
      __syncthreads();
      if (tid < TRm){
        float la;
        float z = spline_fwd(pbuf + tid*LDP, sZ[tid], &la);
        sZ[tid] = z;
        sLad[tid] += la;
      }
      __syncthreads();
    }
  }

  if (tid < TRm){
    float z = sZ[tid];
    out[row0 + tid] = -0.5f * z * z - 0.91893853320467274f + sLad[tid];
  }
}

// ---------------- launch ----------------
extern "C" void kernel_launch(void* const* d_in, const int* in_sizes, int n_in,
                              void* d_out, int out_size){
  const float* y      = (const float*)d_in[0];
  const float* ctx    = (const float*)d_in[1];
  const float* eW1    = (const float*)d_in[2];
  const float* eb1    = (const float*)d_in[3];
  const float* eW2    = (const float*)d_in[4];
  const float* eb2    = (const float*)d_in[5];
  const float* eW3    = (const float*)d_in[6];
  const float* eb3    = (const float*)d_in[7];
  const float* init_b = (const float*)d_in[8];
  const float* ctx_W  = (const float*)d_in[9];
  const float* ctx_b  = (const float*)d_in[10];
  const float* bW1    = (const float*)d_in[11];
  const float* bb1    = (const float*)d_in[12];
  const float* bW2    = (const float*)d_in[13];
  const float* bb2    = (const float*)d_in[14];
  const float* bWc    = (const float*)d_in[15];
  const float* bbc    = (const float*)d_in[16];
  const float* out_W  = (const float*)d_in[17];
  const float* out_b  = (const float*)d_in[18];

  prep_kernel<<<NLAYER*832, 128>>>(ctx_W, bW1, bW2, bWc, out_W);

  int B = in_sizes[0];
  int grid = (B + TRm - 1) / TRm;
  cudaFuncSetAttribute(nsf_kernel, cudaFuncAttributeMaxDynamicSharedMemorySize, SMEM_B);
  nsf_kernel<<<grid, THREADS, SMEM_B>>>(y, ctx, eW1, eb1, eW2, eb2, eW3, eb3,
                                        init_b, ctx_b, bb1, bb2, bbc, out_b,
                                        (float*)d_out);
}